// round 1
// baseline (speedup 1.0000x reference)
#include <cuda_runtime.h>
#include <math.h>

// ---------------------------------------------------------------------------
// Problem constants
// ---------------------------------------------------------------------------
namespace {
constexpr int HG  = 128;
constexpr int WG  = 128;
constexpr int NQ  = HG * WG;        // 16384
constexpr int D   = 256;
constexpr int NHD = 8;
constexpr int CINC = 384;

// Scratch (device globals — no allocation allowed)
__device__ float g_tmp [NQ * D];
__device__ float g_q   [NQ * D];
__device__ float g_v   [NQ * D];
__device__ float g_pos [NQ * D];
__device__ float g_qp  [NQ * D];
__device__ float g_val [NQ * D];
__device__ float g_samp[NQ * D];
__device__ float g_off [NQ * 64];
__device__ float g_aw  [NQ * 32];
__device__ float g_h1  [NQ * 128];
__device__ float g_h2  [NQ * 64];

// ---------------------------------------------------------------------------
// Tiled fp32 GEMM:  C[M,N] = A @ B + bias (+res), optional transposed store.
//   LA == 0 : A[m*K + k]   (row-major activations)
//   LA == 1 : A[k*M + m]   (channel-major conv input)
//   LB == 0 : B[k*N + n]   ((in,out) weight)
//   LB == 1 : B[n*K + k]   ((out,in) conv weight)
// Block tile 64x64, threads 256 (16x16), microtile 4x4, K-tile 16.
// Requires: M % 64 == 0, K % 16 == 0, N % 4 == 0 (N may be < 64).
// ---------------------------------------------------------------------------
template<int LA, int LB, bool RES, bool STORE_T>
__global__ void gemm64(const float* __restrict__ A, const float* __restrict__ B,
                       const float* __restrict__ bias, const float* __restrict__ res,
                       float* __restrict__ C, int M, int N, int K)
{
    __shared__ float sA[16][64];
    __shared__ float sB[16][64];

    const int tid = threadIdx.x;
    const int tx  = tid & 15;
    const int ty  = tid >> 4;
    const int m0  = blockIdx.y * 64;
    const int n0  = blockIdx.x * 64;

    float acc[4][4];
#pragma unroll
    for (int i = 0; i < 4; i++)
#pragma unroll
        for (int j = 0; j < 4; j++) acc[i][j] = 0.f;

    for (int k0 = 0; k0 < K; k0 += 16) {
        // ---- load A tile -> sA[k][m]
        if (LA == 0) {
            const int am = tid >> 2;          // 0..63
            const int ak = (tid & 3) * 4;     // 0,4,8,12
            const float* ap = A + (size_t)(m0 + am) * K + k0 + ak;
#pragma unroll
            for (int j = 0; j < 4; j++) sA[ak + j][am] = ap[j];
        } else {
            const int ak = tid >> 4;          // 0..15
            const int am = (tid & 15) * 4;    // 0..60
            const float4 v4 = *(const float4*)(A + (size_t)(k0 + ak) * M + m0 + am);
            sA[ak][am + 0] = v4.x; sA[ak][am + 1] = v4.y;
            sA[ak][am + 2] = v4.z; sA[ak][am + 3] = v4.w;
        }
        // ---- load B tile -> sB[k][n]
        if (LB == 0) {
            const int bk = tid >> 4;          // 0..15
            const int bn = (tid & 15) * 4;    // 0..60
            if (n0 + bn < N) {
                const float4 v4 = *(const float4*)(B + (size_t)(k0 + bk) * N + n0 + bn);
                sB[bk][bn + 0] = v4.x; sB[bk][bn + 1] = v4.y;
                sB[bk][bn + 2] = v4.z; sB[bk][bn + 3] = v4.w;
            } else {
                sB[bk][bn + 0] = 0.f; sB[bk][bn + 1] = 0.f;
                sB[bk][bn + 2] = 0.f; sB[bk][bn + 3] = 0.f;
            }
        } else {
            const int bn = tid >> 2;          // 0..63
            const int bk = (tid & 3) * 4;
            const float* bp = B + (size_t)(n0 + bn) * K + k0 + bk;
#pragma unroll
            for (int j = 0; j < 4; j++) sB[bk + j][bn] = bp[j];
        }
        __syncthreads();

#pragma unroll
        for (int kk = 0; kk < 16; kk++) {
            const float4 a4 = *(const float4*)&sA[kk][ty * 4];
            const float4 b4 = *(const float4*)&sB[kk][tx * 4];
            const float av[4] = {a4.x, a4.y, a4.z, a4.w};
            const float bv[4] = {b4.x, b4.y, b4.z, b4.w};
#pragma unroll
            for (int i = 0; i < 4; i++)
#pragma unroll
                for (int j = 0; j < 4; j++)
                    acc[i][j] += av[i] * bv[j];
        }
        __syncthreads();
    }

#pragma unroll
    for (int i = 0; i < 4; i++) {
        const int m = m0 + ty * 4 + i;
#pragma unroll
        for (int j = 0; j < 4; j++) {
            const int n = n0 + tx * 4 + j;
            if (n < N) {
                float v = acc[i][j] + bias[n];
                if (RES) v += res[(size_t)m * N + n];
                if (STORE_T) C[(size_t)n * M + m] = v;
                else         C[(size_t)m * N + n] = v;
            }
        }
    }
}

// ---------------------------------------------------------------------------
// Positional embedding: pos[p, d] = d<128 ? col_embed[w, d] : row_embed[h, d-128]
// ---------------------------------------------------------------------------
__global__ void pos_kernel(const float* __restrict__ row_embed,
                           const float* __restrict__ col_embed,
                           float* __restrict__ pos)
{
    const int idx = blockIdx.x * blockDim.x + threadIdx.x;
    if (idx >= NQ * D) return;
    const int p = idx >> 8;
    const int d = idx & 255;
    const int h = p >> 7;
    const int w = p & 127;
    pos[idx] = (d < 128) ? col_embed[w * 128 + d] : row_embed[h * 128 + (d - 128)];
}

__global__ void add_pos_kernel(const float* __restrict__ a,
                               const float* __restrict__ b,
                               float* __restrict__ c)
{
    const int i = blockIdx.x * blockDim.x + threadIdx.x;
    if (i >= NQ * D / 4) return;
    float4 x = ((const float4*)a)[i];
    const float4 y = ((const float4*)b)[i];
    x.x += y.x; x.y += y.y; x.z += y.z; x.w += y.w;
    ((float4*)c)[i] = x;
}

// softmax over NP=4 points per (query, head)
__global__ void softmax4_kernel(float* __restrict__ aw)
{
    const int t = blockIdx.x * blockDim.x + threadIdx.x;
    if (t >= NQ * NHD) return;
    float4 v = ((const float4*)aw)[t];
    const float mx = fmaxf(fmaxf(v.x, v.y), fmaxf(v.z, v.w));
    const float ex = __expf(v.x - mx), ey = __expf(v.y - mx);
    const float ez = __expf(v.z - mx), ew = __expf(v.w - mx);
    const float r = 1.f / (ex + ey + ez + ew);
    ((float4*)aw)[t] = make_float4(ex * r, ey * r, ez * r, ew * r);
}

// ---------------------------------------------------------------------------
// MSDeformAttn bilinear sampling. One warp per (query, head); lane = channel.
//   x = w + off_x ; y = h + off_y   (offset algebra collapses exactly)
// ---------------------------------------------------------------------------
__global__ void msda_sample_kernel(const float* __restrict__ val,
                                   const float* __restrict__ off,
                                   const float* __restrict__ aw,
                                   float* __restrict__ out)
{
    const int warp = (blockIdx.x * blockDim.x + threadIdx.x) >> 5;
    const int lane = threadIdx.x & 31;
    if (warp >= NQ * NHD) return;
    const int p = warp >> 3;
    const int h = warp & 7;
    const int py = p >> 7;
    const int px = p & 127;

    const float* offp  = off + (size_t)p * 64 + h * 8;
    const float* awp   = aw  + (size_t)p * 32 + h * 4;
    const float* vbase = val + h * 32 + lane;

    float acc = 0.f;
#pragma unroll
    for (int k = 0; k < 4; k++) {
        const float a  = awp[k];
        const float x  = (float)px + offp[2 * k + 0];
        const float y  = (float)py + offp[2 * k + 1];
        const float xf = floorf(x), yf = floorf(y);
        const float lx = x - xf,   ly = y - yf;
        const int   x0 = (int)xf,  y0 = (int)yf;

        const float w00 = (1.f - lx) * (1.f - ly) * a;
        const float w01 = lx * (1.f - ly) * a;
        const float w10 = (1.f - lx) * ly * a;
        const float w11 = lx * ly * a;

        const bool xv0 = (x0 >= 0)     && (x0 < WG);
        const bool xv1 = (x0 + 1 >= 0) && (x0 + 1 < WG);
        const bool yv0 = (y0 >= 0)     && (y0 < HG);
        const bool yv1 = (y0 + 1 >= 0) && (y0 + 1 < HG);

        if (yv0 && xv0) acc += w00 * vbase[(size_t)(y0 * WG + x0) * D];
        if (yv0 && xv1) acc += w01 * vbase[(size_t)(y0 * WG + x0 + 1) * D];
        if (yv1 && xv0) acc += w10 * vbase[(size_t)((y0 + 1) * WG + x0) * D];
        if (yv1 && xv1) acc += w11 * vbase[(size_t)((y0 + 1) * WG + x0 + 1) * D];
    }
    out[(size_t)p * D + h * 32 + lane] = acc;
}

// ---------------------------------------------------------------------------
// In-place LayerNorm (+scale/bias) + ReLU; one warp per row.
// ---------------------------------------------------------------------------
template<int WID>
__global__ void ln_relu_kernel(float* __restrict__ x,
                               const float* __restrict__ g,
                               const float* __restrict__ b)
{
    const int row  = (blockIdx.x * blockDim.x + threadIdx.x) >> 5;
    const int lane = threadIdx.x & 31;
    if (row >= NQ) return;
    float* xr = x + (size_t)row * WID;
    constexpr int PER = WID / 32;
    float v[PER];
    float s = 0.f, s2 = 0.f;
#pragma unroll
    for (int i = 0; i < PER; i++) {
        v[i] = xr[lane + 32 * i];
        s  += v[i];
        s2 += v[i] * v[i];
    }
#pragma unroll
    for (int o = 16; o > 0; o >>= 1) {
        s  += __shfl_xor_sync(0xffffffffu, s,  o);
        s2 += __shfl_xor_sync(0xffffffffu, s2, o);
    }
    const float mean = s / WID;
    const float var  = s2 / WID - mean * mean;
    const float inv  = rsqrtf(var + 1e-5f);
#pragma unroll
    for (int i = 0; i < PER; i++) {
        const int c = lane + 32 * i;
        const float o = (v[i] - mean) * inv * g[c] + b[c];
        xr[c] = fmaxf(o, 0.f);
    }
}

float* devptr(const void* symbol)
{
    void* p = nullptr;
    cudaGetSymbolAddress(&p, symbol);
    return (float*)p;
}

} // anonymous namespace

// ---------------------------------------------------------------------------
// Launch sequence
// ---------------------------------------------------------------------------
extern "C" void kernel_launch(void* const* d_in, const int* in_sizes, int n_in,
                              void* d_out, int out_size)
{
    const float* query      = (const float*)d_in[0];
    const float* value      = (const float*)d_in[1];
    const float* conv_q_w   = (const float*)d_in[2];
    const float* conv_q_b   = (const float*)d_in[3];
    const float* conv_v_w   = (const float*)d_in[4];
    const float* conv_v_b   = (const float*)d_in[5];
    const float* row_embed  = (const float*)d_in[6];
    const float* col_embed  = (const float*)d_in[7];
    const float* lin_q_w    = (const float*)d_in[8];
    const float* lin_q_b    = (const float*)d_in[9];
    const float* lin_v_w    = (const float*)d_in[10];
    const float* lin_v_b    = (const float*)d_in[11];
    const float* msda_off_w = (const float*)d_in[12];
    const float* msda_off_b = (const float*)d_in[13];
    const float* msda_aw_w  = (const float*)d_in[14];
    const float* msda_aw_b  = (const float*)d_in[15];
    const float* msda_vp_w  = (const float*)d_in[16];
    const float* msda_vp_b  = (const float*)d_in[17];
    const float* msda_op_w  = (const float*)d_in[18];
    const float* msda_op_b  = (const float*)d_in[19];
    const float* out_w1     = (const float*)d_in[20];
    const float* out_b1     = (const float*)d_in[21];
    const float* ln1_g      = (const float*)d_in[22];
    const float* ln1_b      = (const float*)d_in[23];
    const float* out_w2     = (const float*)d_in[24];
    const float* out_b2     = (const float*)d_in[25];
    const float* ln2_g      = (const float*)d_in[26];
    const float* ln2_b      = (const float*)d_in[27];
    const float* out_w3     = (const float*)d_in[28];
    const float* out_b3     = (const float*)d_in[29];

    float* tmp  = devptr(g_tmp);
    float* q    = devptr(g_q);
    float* v    = devptr(g_v);
    float* pos  = devptr(g_pos);
    float* qp   = devptr(g_qp);
    float* valb = devptr(g_val);
    float* samp = devptr(g_samp);
    float* offb = devptr(g_off);
    float* awb  = devptr(g_aw);
    float* h1   = devptr(g_h1);
    float* h2   = devptr(g_h2);

    const dim3 blk(256);
    auto ggrid = [](int M, int N) { return dim3((N + 63) / 64, (M + 63) / 64); };

    // positional embedding
    pos_kernel<<<(NQ * D + 255) / 256, blk>>>(row_embed, col_embed, pos);

    // input projections:  conv (channel-major A, (out,in) W) then linear
    gemm64<1, 1, false, false><<<ggrid(NQ, D), blk>>>(query, conv_q_w, conv_q_b, nullptr, tmp, NQ, D, CINC);
    gemm64<0, 0, false, false><<<ggrid(NQ, D), blk>>>(tmp, lin_q_w, lin_q_b, nullptr, q, NQ, D, D);
    gemm64<1, 1, false, false><<<ggrid(NQ, D), blk>>>(value, conv_v_w, conv_v_b, nullptr, tmp, NQ, D, CINC);
    gemm64<0, 0, false, false><<<ggrid(NQ, D), blk>>>(tmp, lin_v_w, lin_v_b, nullptr, v, NQ, D, D);

    // 4 MSDeformAttn layers (3 cross + 1 self)
    for (int i = 0; i < 4; i++) {
        const float* vin = (i < 3) ? v : q;

        add_pos_kernel<<<(NQ * D / 4 + 255) / 256, blk>>>(q, pos, qp);

        gemm64<0, 0, false, false><<<ggrid(NQ, D), blk>>>(
            vin, msda_vp_w + (size_t)i * D * D, msda_vp_b + (size_t)i * D, nullptr, valb, NQ, D, D);

        gemm64<0, 0, false, false><<<ggrid(NQ, 64), blk>>>(
            qp, msda_off_w + (size_t)i * D * 64, msda_off_b + (size_t)i * 64, nullptr, offb, NQ, 64, D);

        gemm64<0, 0, false, false><<<ggrid(NQ, 32), blk>>>(
            qp, msda_aw_w + (size_t)i * D * 32, msda_aw_b + (size_t)i * 32, nullptr, awb, NQ, 32, D);

        softmax4_kernel<<<(NQ * NHD + 255) / 256, blk>>>(awb);

        msda_sample_kernel<<<(NQ * NHD * 32 + 255) / 256, blk>>>(valb, offb, awb, samp);

        gemm64<0, 0, true, false><<<ggrid(NQ, D), blk>>>(
            samp, msda_op_w + (size_t)i * D * D, msda_op_b + (size_t)i * D, q, q, NQ, D, D);
    }

    // output MLP: 256 -> 128 (LN+ReLU) -> 64 (LN+ReLU) -> 384 (transposed store)
    gemm64<0, 0, false, false><<<ggrid(NQ, 128), blk>>>(q, out_w1, out_b1, nullptr, h1, NQ, 128, D);
    ln_relu_kernel<128><<<(NQ * 32 + 255) / 256, blk>>>(h1, ln1_g, ln1_b);
    gemm64<0, 0, false, false><<<ggrid(NQ, 64), blk>>>(h1, out_w2, out_b2, nullptr, h2, NQ, 64, 128);
    ln_relu_kernel<64><<<(NQ * 32 + 255) / 256, blk>>>(h2, ln2_g, ln2_b);
    gemm64<0, 0, false, true><<<ggrid(NQ, CINC), blk>>>(h2, out_w3, out_b3, nullptr, (float*)d_out, NQ, CINC, 64);
}

// round 2
// speedup vs baseline: 1.2440x; 1.2440x over previous
#include <cuda_runtime.h>
#include <math.h>

// ---------------------------------------------------------------------------
// Problem constants
// ---------------------------------------------------------------------------
namespace {
constexpr int HG  = 128;
constexpr int WG  = 128;
constexpr int NQ  = HG * WG;        // 16384
constexpr int D   = 256;
constexpr int NHD = 8;
constexpr int CINC = 384;

// Scratch (device globals — no allocation allowed)
__device__ float g_tmp [NQ * D];
__device__ float g_q   [NQ * D];
__device__ float g_v   [NQ * D];
__device__ float g_pos [NQ * D];
__device__ float g_qp  [NQ * D];
__device__ float g_val [NQ * D];
__device__ float g_samp[NQ * D];
__device__ float g_off [NQ * 64];
__device__ float g_aw  [NQ * 32];
__device__ float g_h1  [NQ * 128];
__device__ float g_h2  [NQ * 64];

// ---------------------------------------------------------------------------
// High-intensity fp32 GEMM: C[M,N] = A@B + bias (+res), optional transposed
// store. Block tile 128xBN, K-tile 16, 256 threads, 8x(BN/16) microtile,
// double-buffered smem with register-staged global prefetch.
//   LA == 0 : A[m*K + k]      LA == 1 : A[k*M + m]  (channel-major)
//   LB == 0 : B[k*N + n]      LB == 1 : B[n*K + k]  ((out,in) conv weight)
// Requires: M % 128 == 0, K % 16 == 0. N may be < BN (guarded, LB==0 only).
// ---------------------------------------------------------------------------
template<int LA, int LB, int BN, bool RES, bool STORE_T>
__global__ void __launch_bounds__(256, 2)
gemm_big(const float* __restrict__ A, const float* __restrict__ B,
         const float* __restrict__ bias, const float* __restrict__ res,
         float* __restrict__ C, int M, int N, int K)
{
    constexpr int BM = 128, BK = 16;
    constexpr int TN  = BN / 16;           // 8 or 4
    constexpr int NPB = BN * BK / (4 * 256); // B float4 per thread: 2 or 1

    __shared__ float sA[2][BK][BM];
    __shared__ float sB[2][BK][BN];

    const int tid = threadIdx.x;
    const int tx  = tid & 15;
    const int ty  = tid >> 4;
    const int m0  = blockIdx.y * BM;
    const int n0  = blockIdx.x * BN;

    float4 pa0, pa1;
    float4 pb[NPB];

    // ---- global loads into registers ------------------------------------
    auto loadA = [&](int k0) {
        if constexpr (LA == 0) {
            const int r  = tid >> 2;
            const int c4 = (tid & 3) * 4;
            const float* p = A + (size_t)(m0 + r) * K + k0 + c4;
            pa0 = *(const float4*)p;
            pa1 = *(const float4*)(p + (size_t)64 * K);
        } else {
            const int k  = tid >> 5;
            const int mc = (tid & 31) * 4;
            const float* p = A + (size_t)(k0 + k) * M + m0 + mc;
            pa0 = *(const float4*)p;
            pa1 = *(const float4*)(p + (size_t)8 * M);
        }
    };
    auto loadB = [&](int k0) {
        if constexpr (LB == 0) {
#pragma unroll
            for (int i = 0; i < NPB; i++) {
                const int idx = tid + i * 256;
                const int k   = idx / (BN / 4);
                const int c   = (idx % (BN / 4)) * 4;
                if (n0 + c < N)
                    pb[i] = *(const float4*)(B + (size_t)(k0 + k) * N + n0 + c);
                else
                    pb[i] = make_float4(0.f, 0.f, 0.f, 0.f);
            }
        } else {
#pragma unroll
            for (int i = 0; i < NPB; i++) {
                const int idx = tid + i * 256;
                const int n   = idx & 127;
                const int c   = (idx >> 7) * 4;
                pb[i] = *(const float4*)(B + (size_t)(n0 + n) * K + k0 + c);
            }
        }
    };
    // ---- register -> shared ---------------------------------------------
    auto stsA = [&](int s) {
        if constexpr (LA == 0) {
            const int r  = tid >> 2;
            const int c4 = (tid & 3) * 4;
            sA[s][c4 + 0][r] = pa0.x; sA[s][c4 + 1][r] = pa0.y;
            sA[s][c4 + 2][r] = pa0.z; sA[s][c4 + 3][r] = pa0.w;
            sA[s][c4 + 0][r + 64] = pa1.x; sA[s][c4 + 1][r + 64] = pa1.y;
            sA[s][c4 + 2][r + 64] = pa1.z; sA[s][c4 + 3][r + 64] = pa1.w;
        } else {
            const int k  = tid >> 5;
            const int mc = (tid & 31) * 4;
            *(float4*)&sA[s][k][mc]     = pa0;
            *(float4*)&sA[s][k + 8][mc] = pa1;
        }
    };
    auto stsB = [&](int s) {
        if constexpr (LB == 0) {
#pragma unroll
            for (int i = 0; i < NPB; i++) {
                const int idx = tid + i * 256;
                const int k   = idx / (BN / 4);
                const int c   = (idx % (BN / 4)) * 4;
                *(float4*)&sB[s][k][c] = pb[i];
            }
        } else {
#pragma unroll
            for (int i = 0; i < NPB; i++) {
                const int idx = tid + i * 256;
                const int n   = idx & 127;
                const int c   = (idx >> 7) * 4;
                sB[s][c + 0][n] = pb[i].x; sB[s][c + 1][n] = pb[i].y;
                sB[s][c + 2][n] = pb[i].z; sB[s][c + 3][n] = pb[i].w;
            }
        }
    };

    float acc[8][TN];
#pragma unroll
    for (int i = 0; i < 8; i++)
#pragma unroll
        for (int j = 0; j < TN; j++) acc[i][j] = 0.f;

    loadA(0);
    loadB(0);

    int stage = 0;
    for (int k0 = 0; k0 < K; k0 += BK) {
        stsA(stage);
        stsB(stage);
        __syncthreads();
        if (k0 + BK < K) { loadA(k0 + BK); loadB(k0 + BK); }

#pragma unroll
        for (int kk = 0; kk < BK; kk++) {
            float a[8], b[TN];
            *(float4*)&a[0] = *(const float4*)&sA[stage][kk][ty * 8];
            *(float4*)&a[4] = *(const float4*)&sA[stage][kk][ty * 8 + 4];
#pragma unroll
            for (int jv = 0; jv < TN / 4; jv++)
                *(float4*)&b[jv * 4] = *(const float4*)&sB[stage][kk][tx * TN + jv * 4];
#pragma unroll
            for (int i = 0; i < 8; i++)
#pragma unroll
                for (int j = 0; j < TN; j++)
                    acc[i][j] += a[i] * b[j];
        }
        stage ^= 1;
    }

    // ---- epilogue --------------------------------------------------------
    float bs[TN];
#pragma unroll
    for (int j = 0; j < TN; j++) {
        const int n = n0 + tx * TN + j;
        bs[j] = (n < N) ? bias[n] : 0.f;
    }

    if (STORE_T) {
        // C[n * M + m], 8 consecutive m per thread -> 2 float4 per column
#pragma unroll
        for (int j = 0; j < TN; j++) {
            const int n = n0 + tx * TN + j;
            if (n < N) {
                float4 v0 = make_float4(acc[0][j] + bs[j], acc[1][j] + bs[j],
                                        acc[2][j] + bs[j], acc[3][j] + bs[j]);
                float4 v1 = make_float4(acc[4][j] + bs[j], acc[5][j] + bs[j],
                                        acc[6][j] + bs[j], acc[7][j] + bs[j]);
                float* cp = C + (size_t)n * M + m0 + ty * 8;
                *(float4*)cp       = v0;
                *(float4*)(cp + 4) = v1;
            }
        }
    } else if (n0 + BN <= N) {
        // full-tile fast path, vectorized
#pragma unroll
        for (int i = 0; i < 8; i++) {
            const int m = m0 + ty * 8 + i;
            float* cp = C + (size_t)m * N + n0 + tx * TN;
#pragma unroll
            for (int jv = 0; jv < TN / 4; jv++) {
                float4 v;
                v.x = acc[i][jv * 4 + 0] + bs[jv * 4 + 0];
                v.y = acc[i][jv * 4 + 1] + bs[jv * 4 + 1];
                v.z = acc[i][jv * 4 + 2] + bs[jv * 4 + 2];
                v.w = acc[i][jv * 4 + 3] + bs[jv * 4 + 3];
                if (RES) {
                    const float4 r4 = *(const float4*)(res + (size_t)m * N + n0 + tx * TN + jv * 4);
                    v.x += r4.x; v.y += r4.y; v.z += r4.z; v.w += r4.w;
                }
                *(float4*)(cp + jv * 4) = v;
            }
        }
    } else {
        // partial tile (aw GEMM: N=32 < BN=64)
#pragma unroll
        for (int i = 0; i < 8; i++) {
            const int m = m0 + ty * 8 + i;
#pragma unroll
            for (int j = 0; j < TN; j++) {
                const int n = n0 + tx * TN + j;
                if (n < N) {
                    float v = acc[i][j] + bs[j];
                    if (RES) v += res[(size_t)m * N + n];
                    C[(size_t)m * N + n] = v;
                }
            }
        }
    }
}

// ---------------------------------------------------------------------------
// Positional embedding: pos[p, d] = d<128 ? col_embed[w, d] : row_embed[h, d-128]
// ---------------------------------------------------------------------------
__global__ void pos_kernel(const float* __restrict__ row_embed,
                           const float* __restrict__ col_embed,
                           float* __restrict__ pos)
{
    const int idx = blockIdx.x * blockDim.x + threadIdx.x;
    if (idx >= NQ * D) return;
    const int p = idx >> 8;
    const int d = idx & 255;
    const int h = p >> 7;
    const int w = p & 127;
    pos[idx] = (d < 128) ? col_embed[w * 128 + d] : row_embed[h * 128 + (d - 128)];
}

__global__ void add_pos_kernel(const float* __restrict__ a,
                               const float* __restrict__ b,
                               float* __restrict__ c)
{
    const int i = blockIdx.x * blockDim.x + threadIdx.x;
    if (i >= NQ * D / 4) return;
    float4 x = ((const float4*)a)[i];
    const float4 y = ((const float4*)b)[i];
    x.x += y.x; x.y += y.y; x.z += y.z; x.w += y.w;
    ((float4*)c)[i] = x;
}

// softmax over NP=4 points per (query, head)
__global__ void softmax4_kernel(float* __restrict__ aw)
{
    const int t = blockIdx.x * blockDim.x + threadIdx.x;
    if (t >= NQ * NHD) return;
    float4 v = ((const float4*)aw)[t];
    const float mx = fmaxf(fmaxf(v.x, v.y), fmaxf(v.z, v.w));
    const float ex = __expf(v.x - mx), ey = __expf(v.y - mx);
    const float ez = __expf(v.z - mx), ew = __expf(v.w - mx);
    const float r = 1.f / (ex + ey + ez + ew);
    ((float4*)aw)[t] = make_float4(ex * r, ey * r, ez * r, ew * r);
}

// ---------------------------------------------------------------------------
// MSDeformAttn bilinear sampling. One warp per (query, head); lane = channel.
// ---------------------------------------------------------------------------
__global__ void msda_sample_kernel(const float* __restrict__ val,
                                   const float* __restrict__ off,
                                   const float* __restrict__ aw,
                                   float* __restrict__ out)
{
    const int warp = (blockIdx.x * blockDim.x + threadIdx.x) >> 5;
    const int lane = threadIdx.x & 31;
    if (warp >= NQ * NHD) return;
    const int p = warp >> 3;
    const int h = warp & 7;
    const int py = p >> 7;
    const int px = p & 127;

    const float* offp  = off + (size_t)p * 64 + h * 8;
    const float* awp   = aw  + (size_t)p * 32 + h * 4;
    const float* vbase = val + h * 32 + lane;

    float acc = 0.f;
#pragma unroll
    for (int k = 0; k < 4; k++) {
        const float a  = awp[k];
        const float x  = (float)px + offp[2 * k + 0];
        const float y  = (float)py + offp[2 * k + 1];
        const float xf = floorf(x), yf = floorf(y);
        const float lx = x - xf,   ly = y - yf;
        const int   x0 = (int)xf,  y0 = (int)yf;

        const float w00 = (1.f - lx) * (1.f - ly) * a;
        const float w01 = lx * (1.f - ly) * a;
        const float w10 = (1.f - lx) * ly * a;
        const float w11 = lx * ly * a;

        const bool xv0 = (x0 >= 0)     && (x0 < WG);
        const bool xv1 = (x0 + 1 >= 0) && (x0 + 1 < WG);
        const bool yv0 = (y0 >= 0)     && (y0 < HG);
        const bool yv1 = (y0 + 1 >= 0) && (y0 + 1 < HG);

        if (yv0 && xv0) acc += w00 * vbase[(size_t)(y0 * WG + x0) * D];
        if (yv0 && xv1) acc += w01 * vbase[(size_t)(y0 * WG + x0 + 1) * D];
        if (yv1 && xv0) acc += w10 * vbase[(size_t)((y0 + 1) * WG + x0) * D];
        if (yv1 && xv1) acc += w11 * vbase[(size_t)((y0 + 1) * WG + x0 + 1) * D];
    }
    out[(size_t)p * D + h * 32 + lane] = acc;
}

// ---------------------------------------------------------------------------
// In-place LayerNorm (+scale/bias) + ReLU; one warp per row.
// ---------------------------------------------------------------------------
template<int WID>
__global__ void ln_relu_kernel(float* __restrict__ x,
                               const float* __restrict__ g,
                               const float* __restrict__ b)
{
    const int row  = (blockIdx.x * blockDim.x + threadIdx.x) >> 5;
    const int lane = threadIdx.x & 31;
    if (row >= NQ) return;
    float* xr = x + (size_t)row * WID;
    constexpr int PER = WID / 32;
    float v[PER];
    float s = 0.f, s2 = 0.f;
#pragma unroll
    for (int i = 0; i < PER; i++) {
        v[i] = xr[lane + 32 * i];
        s  += v[i];
        s2 += v[i] * v[i];
    }
#pragma unroll
    for (int o = 16; o > 0; o >>= 1) {
        s  += __shfl_xor_sync(0xffffffffu, s,  o);
        s2 += __shfl_xor_sync(0xffffffffu, s2, o);
    }
    const float mean = s / WID;
    const float var  = s2 / WID - mean * mean;
    const float inv  = rsqrtf(var + 1e-5f);
#pragma unroll
    for (int i = 0; i < PER; i++) {
        const int c = lane + 32 * i;
        const float o = (v[i] - mean) * inv * g[c] + b[c];
        xr[c] = fmaxf(o, 0.f);
    }
}

float* devptr(const void* symbol)
{
    void* p = nullptr;
    cudaGetSymbolAddress(&p, symbol);
    return (float*)p;
}

} // anonymous namespace

// ---------------------------------------------------------------------------
// Launch sequence
// ---------------------------------------------------------------------------
extern "C" void kernel_launch(void* const* d_in, const int* in_sizes, int n_in,
                              void* d_out, int out_size)
{
    const float* query      = (const float*)d_in[0];
    const float* value      = (const float*)d_in[1];
    const float* conv_q_w   = (const float*)d_in[2];
    const float* conv_q_b   = (const float*)d_in[3];
    const float* conv_v_w   = (const float*)d_in[4];
    const float* conv_v_b   = (const float*)d_in[5];
    const float* row_embed  = (const float*)d_in[6];
    const float* col_embed  = (const float*)d_in[7];
    const float* lin_q_w    = (const float*)d_in[8];
    const float* lin_q_b    = (const float*)d_in[9];
    const float* lin_v_w    = (const float*)d_in[10];
    const float* lin_v_b    = (const float*)d_in[11];
    const float* msda_off_w = (const float*)d_in[12];
    const float* msda_off_b = (const float*)d_in[13];
    const float* msda_aw_w  = (const float*)d_in[14];
    const float* msda_aw_b  = (const float*)d_in[15];
    const float* msda_vp_w  = (const float*)d_in[16];
    const float* msda_vp_b  = (const float*)d_in[17];
    const float* msda_op_w  = (const float*)d_in[18];
    const float* msda_op_b  = (const float*)d_in[19];
    const float* out_w1     = (const float*)d_in[20];
    const float* out_b1     = (const float*)d_in[21];
    const float* ln1_g      = (const float*)d_in[22];
    const float* ln1_b      = (const float*)d_in[23];
    const float* out_w2     = (const float*)d_in[24];
    const float* out_b2     = (const float*)d_in[25];
    const float* ln2_g      = (const float*)d_in[26];
    const float* ln2_b      = (const float*)d_in[27];
    const float* out_w3     = (const float*)d_in[28];
    const float* out_b3     = (const float*)d_in[29];

    float* tmp  = devptr(g_tmp);
    float* q    = devptr(g_q);
    float* v    = devptr(g_v);
    float* pos  = devptr(g_pos);
    float* qp   = devptr(g_qp);
    float* valb = devptr(g_val);
    float* samp = devptr(g_samp);
    float* offb = devptr(g_off);
    float* awb  = devptr(g_aw);
    float* h1   = devptr(g_h1);
    float* h2   = devptr(g_h2);

    const dim3 blk(256);

    // positional embedding
    pos_kernel<<<(NQ * D + 255) / 256, blk>>>(row_embed, col_embed, pos);

    // input projections: conv (channel-major A, (out,in) W) then linear
    gemm_big<1, 1, 128, false, false><<<dim3(2, 128), blk>>>(query, conv_q_w, conv_q_b, nullptr, tmp, NQ, D, CINC);
    gemm_big<0, 0, 128, false, false><<<dim3(2, 128), blk>>>(tmp, lin_q_w, lin_q_b, nullptr, q, NQ, D, D);
    gemm_big<1, 1, 128, false, false><<<dim3(2, 128), blk>>>(value, conv_v_w, conv_v_b, nullptr, tmp, NQ, D, CINC);
    gemm_big<0, 0, 128, false, false><<<dim3(2, 128), blk>>>(tmp, lin_v_w, lin_v_b, nullptr, v, NQ, D, D);

    // 4 MSDeformAttn layers (3 cross + 1 self)
    for (int i = 0; i < 4; i++) {
        const float* vin = (i < 3) ? v : q;

        add_pos_kernel<<<(NQ * D / 4 + 255) / 256, blk>>>(q, pos, qp);

        gemm_big<0, 0, 128, false, false><<<dim3(2, 128), blk>>>(
            vin, msda_vp_w + (size_t)i * D * D, msda_vp_b + (size_t)i * D, nullptr, valb, NQ, D, D);

        gemm_big<0, 0, 64, false, false><<<dim3(1, 128), blk>>>(
            qp, msda_off_w + (size_t)i * D * 64, msda_off_b + (size_t)i * 64, nullptr, offb, NQ, 64, D);

        gemm_big<0, 0, 64, false, false><<<dim3(1, 128), blk>>>(
            qp, msda_aw_w + (size_t)i * D * 32, msda_aw_b + (size_t)i * 32, nullptr, awb, NQ, 32, D);

        softmax4_kernel<<<(NQ * NHD + 255) / 256, blk>>>(awb);

        msda_sample_kernel<<<(NQ * NHD * 32 + 255) / 256, blk>>>(valb, offb, awb, samp);

        gemm_big<0, 0, 128, true, false><<<dim3(2, 128), blk>>>(
            samp, msda_op_w + (size_t)i * D * D, msda_op_b + (size_t)i * D, q, q, NQ, D, D);
    }

    // output MLP: 256 -> 128 (LN+ReLU) -> 64 (LN+ReLU) -> 384 (transposed store)
    gemm_big<0, 0, 128, false, false><<<dim3(1, 128), blk>>>(q, out_w1, out_b1, nullptr, h1, NQ, 128, D);
    ln_relu_kernel<128><<<(NQ * 32 + 255) / 256, blk>>>(h1, ln1_g, ln1_b);
    gemm_big<0, 0, 64, false, false><<<dim3(1, 128), blk>>>(h1, out_w2, out_b2, nullptr, h2, NQ, 64, 128);
    ln_relu_kernel<64><<<(NQ * 32 + 255) / 256, blk>>>(h2, ln2_g, ln2_b);
    gemm_big<0, 0, 128, false, true><<<dim3(3, 128), blk>>>(h2, out_w3, out_b3, nullptr, (float*)d_out, NQ, CINC, 64);
}

// round 11
// speedup vs baseline: 1.9467x; 1.5648x over previous
#include <cuda_runtime.h>
#include <cuda_bf16.h>
#include <cstdint>
#include <math.h>

namespace {

// ===========================================================================
// Warp-MMA helpers (baseline PTX, works on plain sm_103 target)
// ===========================================================================
__device__ __forceinline__ uint32_t smem_to_u32(const void* smem_ptr) {
    uint32_t addr;
    asm("{ .reg .u64 tmp; cvta.to.shared.u64 tmp, %1; cvt.u32.u64 %0, tmp; }"
        : "=r"(addr) : "l"(smem_ptr));
    return addr;
}

#define SMEM_SWIZZLE_128B(byte_offset) \
    ((byte_offset) ^ (((byte_offset) >> 3) & 0x70))

__device__ __forceinline__ void ldsm4(uint32_t* r, uint32_t addr) {
    asm volatile("ldmatrix.sync.aligned.m8n8.x4.shared.b16 {%0,%1,%2,%3}, [%4];"
                 : "=r"(r[0]), "=r"(r[1]), "=r"(r[2]), "=r"(r[3]) : "r"(addr));
}

__device__ __forceinline__ void mma16816(float* c, const uint32_t* a, const uint32_t* b) {
    asm volatile(
        "mma.sync.aligned.m16n8k16.row.col.f32.bf16.bf16.f32 "
        "{%0,%1,%2,%3}, {%4,%5,%6,%7}, {%8,%9}, {%0,%1,%2,%3};"
        : "+f"(c[0]), "+f"(c[1]), "+f"(c[2]), "+f"(c[3])
        : "r"(a[0]), "r"(a[1]), "r"(a[2]), "r"(a[3]), "r"(b[0]), "r"(b[1]));
}

// ===========================================================================
// Problem constants + scratch
// ===========================================================================
constexpr int HG  = 128;
constexpr int WG  = 128;
constexpr int NQ  = HG * WG;        // 16384
constexpr int D   = 256;
constexpr int NHD = 8;
constexpr int CINC = 384;

// converted-weight buffer offsets (elements)
constexpr int W_CONVQ = 0;                       // 256x384
constexpr int W_CONVV = 98304;                   // 256x384
constexpr int W_LINQ  = 196608;                  // 256x256
constexpr int W_LINV  = 262144;                  // 256x256
constexpr int W_VP    = 327680;                  // 4 x 256x256
constexpr int W_OFF   = 589824;                  // 4 x 64x256
constexpr int W_AW    = 655360;                  // 4 x 32x256
constexpr int W_OP    = 688128;                  // 4 x 256x256
constexpr int W_O1    = 950272;                  // 128x256
constexpr int W_O2    = 983040;                  // 64x128
constexpr int W_O3    = 991232;                  // 384x64
constexpr int W_TOTAL = 1015808;

// fp32 scratch
__device__ float g_pos [NQ * D];
__device__ float g_q   [NQ * D];
__device__ float g_val [NQ * D];
__device__ float g_off [NQ * 64];
__device__ float g_aw  [NQ * 32];
__device__ float g_h1f [NQ * 128];
__device__ float g_h2f [NQ * 64];

// bf16 hi/lo scratch
__device__ __nv_bfloat16 g_cq_h[NQ * CINC], g_cq_l[NQ * CINC];
__device__ __nv_bfloat16 g_cv_h[NQ * CINC], g_cv_l[NQ * CINC];
__device__ __nv_bfloat16 g_t_h [NQ * D],    g_t_l [NQ * D];
__device__ __nv_bfloat16 g_vb_h[NQ * D],    g_vb_l[NQ * D];
__device__ __nv_bfloat16 g_qb_h[NQ * D],    g_qb_l[NQ * D];
__device__ __nv_bfloat16 g_qp_h[NQ * D],    g_qp_l[NQ * D];
__device__ __nv_bfloat16 g_sp_h[NQ * D],    g_sp_l[NQ * D];
__device__ __nv_bfloat16 g_h1_h[NQ * 128],  g_h1_l[NQ * 128];
__device__ __nv_bfloat16 g_h2_h[NQ * 64],   g_h2_l[NQ * 64];
__device__ __nv_bfloat16 g_w_h [W_TOTAL],   g_w_l [W_TOTAL];

__device__ __forceinline__ void f2bf2(float v, __nv_bfloat16& h, __nv_bfloat16& l)
{
    h = __float2bfloat16(v);
    l = __float2bfloat16(v - __bfloat162float(h));
}

// ===========================================================================
// Tensor-core split-bf16 GEMM via mma.sync:
//   C[M,N] = A@B^T + bias (+res), A hi/lo [M,K] row, B hi/lo [N,K] row.
//   Block tile 128 x BN, 8 warps (4m x 2n), warp tile 32 x (BN/2).
//   K-chunk 64 halves (one SW128 row of 128 bytes), smem-staged.
//   3 products: hi*hi + hi*lo + lo*hi, fp32 accumulate in registers.
// ===========================================================================
template<int BN, bool WF32, bool WBF16, bool RES, bool STORE_T>
__global__ void __launch_bounds__(256)
gemm_mma(const __nv_bfloat16* __restrict__ Ahi, const __nv_bfloat16* __restrict__ Alo,
         const __nv_bfloat16* __restrict__ Bhi, const __nv_bfloat16* __restrict__ Blo,
         const float* __restrict__ bias, const float* __restrict__ res,
         float* __restrict__ C, __nv_bfloat16* __restrict__ Chi,
         __nv_bfloat16* __restrict__ Clo, int M, int N, int K)
{
    constexpr int WNT = BN / 2;      // warp n-tile (32 or 16)
    constexpr int NF  = WNT / 8;     // n8 fragments per warp (4 or 2)

    __shared__ char sA[2][128 * 128];   // [half(hi/lo)][row*128B], SW128
    __shared__ char sB[2][BN * 128];

    const int tid  = threadIdx.x;
    const int lane = tid & 31;
    const int wid  = tid >> 5;
    const int wm   = wid & 3;        // warp m index (0..3)
    const int wn   = wid >> 2;       // warp n index (0..1)
    const int m0   = blockIdx.y * 128;
    const int n0   = blockIdx.x * BN;

    const uint32_t sA0 = smem_to_u32(sA[0]);
    const uint32_t sA1 = smem_to_u32(sA[1]);
    const uint32_t sB0 = smem_to_u32(sB[0]);
    const uint32_t sB1 = smem_to_u32(sB[1]);

    float acc[2][NF][4];
#pragma unroll
    for (int i = 0; i < 2; i++)
#pragma unroll
        for (int j = 0; j < NF; j++)
#pragma unroll
            for (int k = 0; k < 4; k++) acc[i][j][k] = 0.f;

    // ldmatrix lane-address components
    const int a_row = (lane & 7) + ((lane >> 3) & 1) * 8;   // row within m16
    const int a_koff = (lane >> 4) * 8;                     // k-half offset
    const int b_row = (lane >> 4) * 8 + (lane & 7);         // n within 16-row pair
    const int b_koff = ((lane >> 3) & 1) * 8;

    const int nchunks = K >> 6;
    for (int c = 0; c < nchunks; c++) {
        const int k0 = c << 6;
        if (c > 0) __syncthreads();
        // ---- load A tile: 2 halves x 128 rows x 128B
#pragma unroll
        for (int u = tid; u < 2048; u += 256) {
            const int half = u >> 10;
            const int uu   = u & 1023;
            const int row  = uu >> 3;
            const int c16  = uu & 7;
            const __nv_bfloat16* src =
                (half ? Alo : Ahi) + (size_t)(m0 + row) * K + k0 + c16 * 8;
            *(uint4*)(sA[half] + SMEM_SWIZZLE_128B(row * 128 + c16 * 16)) =
                *(const uint4*)src;
        }
        // ---- load B tile: 2 halves x BN rows x 128B
#pragma unroll
        for (int u = tid; u < 2 * BN * 8; u += 256) {
            const int half = (u >= BN * 8);
            const int uu   = half ? u - BN * 8 : u;
            const int row  = uu >> 3;
            const int c16  = uu & 7;
            const __nv_bfloat16* src =
                (half ? Blo : Bhi) + (size_t)(n0 + row) * K + k0 + c16 * 8;
            *(uint4*)(sB[half] + SMEM_SWIZZLE_128B(row * 128 + c16 * 16)) =
                *(const uint4*)src;
        }
        __syncthreads();

        // ---- 4 k16 steps
#pragma unroll
        for (int ks = 0; ks < 4; ks++) {
            const int kw = ks * 16;
            uint32_t ah[2][4], al[2][4];
#pragma unroll
            for (int mb = 0; mb < 2; mb++) {
                const int row = wm * 32 + mb * 16 + a_row;
                const uint32_t off = SMEM_SWIZZLE_128B(row * 128 + (kw + a_koff) * 2);
                ldsm4(ah[mb], sA0 + off);
                ldsm4(al[mb], sA1 + off);
            }
            uint32_t bh[NF][2], bl[NF][2];
#pragma unroll
            for (int pr = 0; pr < NF / 2; pr++) {
                const int row = wn * WNT + pr * 16 + b_row;
                const uint32_t off = SMEM_SWIZZLE_128B(row * 128 + (kw + b_koff) * 2);
                uint32_t t[4];
                ldsm4(t, sB0 + off);
                bh[pr * 2][0] = t[0]; bh[pr * 2][1] = t[1];
                bh[pr * 2 + 1][0] = t[2]; bh[pr * 2 + 1][1] = t[3];
                ldsm4(t, sB1 + off);
                bl[pr * 2][0] = t[0]; bl[pr * 2][1] = t[1];
                bl[pr * 2 + 1][0] = t[2]; bl[pr * 2 + 1][1] = t[3];
            }
#pragma unroll
            for (int mb = 0; mb < 2; mb++)
#pragma unroll
                for (int nf = 0; nf < NF; nf++) {
                    mma16816(acc[mb][nf], ah[mb], bh[nf]);
                    mma16816(acc[mb][nf], ah[mb], bl[nf]);
                    mma16816(acc[mb][nf], al[mb], bh[nf]);
                }
        }
    }

    // ---- epilogue ---------------------------------------------------------
#pragma unroll
    for (int mb = 0; mb < 2; mb++) {
#pragma unroll
        for (int part = 0; part < 2; part++) {
            const int m = m0 + wm * 32 + mb * 16 + part * 8 + (lane >> 2);
#pragma unroll
            for (int nf = 0; nf < NF; nf++) {
                const int col = n0 + wn * WNT + nf * 8 + (lane & 3) * 2;
                float v0 = acc[mb][nf][part * 2 + 0] + bias[col];
                float v1 = acc[mb][nf][part * 2 + 1] + bias[col + 1];
                if (RES) {
                    const float2 r2 = *(const float2*)(res + (size_t)m * N + col);
                    v0 += r2.x; v1 += r2.y;
                }
                if (STORE_T) {
                    C[(size_t)col * M + m] = v0;
                    C[(size_t)(col + 1) * M + m] = v1;
                } else if (WF32) {
                    *(float2*)(C + (size_t)m * N + col) = make_float2(v0, v1);
                }
                if (WBF16) {
                    __nv_bfloat16 h0, l0, h1, l1;
                    f2bf2(v0, h0, l0);
                    f2bf2(v1, h1, l1);
                    Chi[(size_t)m * N + col] = h0; Chi[(size_t)m * N + col + 1] = h1;
                    Clo[(size_t)m * N + col] = l0; Clo[(size_t)m * N + col + 1] = l1;
                }
            }
        }
    }
}

// ===========================================================================
// Elementwise / conversion kernels
// ===========================================================================
__global__ void pos_kernel(const float* __restrict__ row_embed,
                           const float* __restrict__ col_embed,
                           float* __restrict__ pos)
{
    const int idx = blockIdx.x * blockDim.x + threadIdx.x;
    if (idx >= NQ * D) return;
    const int p = idx >> 8;
    const int d = idx & 255;
    const int h = p >> 7;
    const int w = p & 127;
    pos[idx] = (d < 128) ? col_embed[w * 128 + d] : row_embed[h * 128 + (d - 128)];
}

// channel-major fp32 [K,M] -> hi/lo bf16 [M,K] (32x32 smem transpose tiles)
__global__ void tconvert_kernel(const float* __restrict__ src,
                                __nv_bfloat16* __restrict__ hi,
                                __nv_bfloat16* __restrict__ lo, int M, int K)
{
    __shared__ float t[32][33];
    const int tx = threadIdx.x, ty = threadIdx.y;
    const int m0 = blockIdx.x * 32, k0 = blockIdx.y * 32;
#pragma unroll
    for (int j = 0; j < 4; j++)
        t[ty + j * 8][tx] = src[(size_t)(k0 + ty + j * 8) * M + m0 + tx];
    __syncthreads();
#pragma unroll
    for (int j = 0; j < 4; j++) {
        const int m = m0 + ty + j * 8;
        const int k = k0 + tx;
        __nv_bfloat16 h, l;
        f2bf2(t[tx][ty + j * 8], h, l);
        hi[(size_t)m * K + k] = h;
        lo[(size_t)m * K + k] = l;
    }
}

// one-shot conversion of all weight matrices into [N,K] hi/lo bf16
struct WSeg { int srcSel; int srcOff; int N; int K; int kn; int dstOff; };
__device__ const WSeg d_wsegs[23] = {
    {0, 0,      256, 384, 0, W_CONVQ},
    {1, 0,      256, 384, 0, W_CONVV},
    {2, 0,      256, 256, 1, W_LINQ},
    {3, 0,      256, 256, 1, W_LINV},
    {4, 0,      256, 256, 1, W_VP + 0 * 65536},
    {4, 65536,  256, 256, 1, W_VP + 1 * 65536},
    {4, 131072, 256, 256, 1, W_VP + 2 * 65536},
    {4, 196608, 256, 256, 1, W_VP + 3 * 65536},
    {5, 0,      64, 256, 1, W_OFF + 0 * 16384},
    {5, 16384,  64, 256, 1, W_OFF + 1 * 16384},
    {5, 32768,  64, 256, 1, W_OFF + 2 * 16384},
    {5, 49152,  64, 256, 1, W_OFF + 3 * 16384},
    {6, 0,      32, 256, 1, W_AW + 0 * 8192},
    {6, 8192,   32, 256, 1, W_AW + 1 * 8192},
    {6, 16384,  32, 256, 1, W_AW + 2 * 8192},
    {6, 24576,  32, 256, 1, W_AW + 3 * 8192},
    {7, 0,      256, 256, 1, W_OP + 0 * 65536},
    {7, 65536,  256, 256, 1, W_OP + 1 * 65536},
    {7, 131072, 256, 256, 1, W_OP + 2 * 65536},
    {7, 196608, 256, 256, 1, W_OP + 3 * 65536},
    {8, 0,      128, 256, 1, W_O1},
    {9, 0,      64, 128, 1, W_O2},
    {10, 0,     384, 64, 1, W_O3},
};
struct WPtrs { const float* p[11]; };

__global__ void convert_weights_kernel(WPtrs ptrs,
                                       __nv_bfloat16* __restrict__ hi,
                                       __nv_bfloat16* __restrict__ lo)
{
    const int id = blockIdx.x * blockDim.x + threadIdx.x;
    if (id >= W_TOTAL) return;
    int s = 0;
#pragma unroll
    for (int i = 1; i < 23; i++)
        if (id >= d_wsegs[i].dstOff) s = i;
    const WSeg seg = d_wsegs[s];
    const int local = id - seg.dstOff;
    const int n = local / seg.K;
    const int k = local - n * seg.K;
    const float* src = ptrs.p[seg.srcSel] + seg.srcOff;
    const float v = seg.kn ? src[(size_t)k * seg.N + n] : src[(size_t)n * seg.K + k];
    __nv_bfloat16 h, l;
    f2bf2(v, h, l);
    hi[id] = h;
    lo[id] = l;
}

__global__ void add_pos_convert_kernel(const float* __restrict__ q,
                                       const float* __restrict__ pos,
                                       __nv_bfloat16* __restrict__ hi,
                                       __nv_bfloat16* __restrict__ lo)
{
    const int i = blockIdx.x * blockDim.x + threadIdx.x;
    if (i >= NQ * D) return;
    __nv_bfloat16 h, l;
    f2bf2(q[i] + pos[i], h, l);
    hi[i] = h;
    lo[i] = l;
}

__global__ void softmax4_kernel(float* __restrict__ aw)
{
    const int t = blockIdx.x * blockDim.x + threadIdx.x;
    if (t >= NQ * NHD) return;
    float4 v = ((const float4*)aw)[t];
    const float mx = fmaxf(fmaxf(v.x, v.y), fmaxf(v.z, v.w));
    const float ex = __expf(v.x - mx), ey = __expf(v.y - mx);
    const float ez = __expf(v.z - mx), ew = __expf(v.w - mx);
    const float r = 1.f / (ex + ey + ez + ew);
    ((float4*)aw)[t] = make_float4(ex * r, ey * r, ez * r, ew * r);
}

// one warp per (query, head); lane = channel; writes samp as bf16 hi/lo
__global__ void msda_sample_kernel(const float* __restrict__ val,
                                   const float* __restrict__ off,
                                   const float* __restrict__ aw,
                                   __nv_bfloat16* __restrict__ ohi,
                                   __nv_bfloat16* __restrict__ olo)
{
    const int warp = (blockIdx.x * blockDim.x + threadIdx.x) >> 5;
    const int lane = threadIdx.x & 31;
    if (warp >= NQ * NHD) return;
    const int p = warp >> 3;
    const int hh = warp & 7;
    const int py = p >> 7;
    const int px = p & 127;

    const float* offp  = off + (size_t)p * 64 + hh * 8;
    const float* awp   = aw  + (size_t)p * 32 + hh * 4;
    const float* vbase = val + hh * 32 + lane;

    float acc = 0.f;
#pragma unroll
    for (int k = 0; k < 4; k++) {
        const float a  = awp[k];
        const float x  = (float)px + offp[2 * k + 0];
        const float y  = (float)py + offp[2 * k + 1];
        const float xf = floorf(x), yf = floorf(y);
        const float lx = x - xf,   ly = y - yf;
        const int   x0 = (int)xf,  y0 = (int)yf;

        const float w00 = (1.f - lx) * (1.f - ly) * a;
        const float w01 = lx * (1.f - ly) * a;
        const float w10 = (1.f - lx) * ly * a;
        const float w11 = lx * ly * a;

        const bool xv0 = (x0 >= 0)     && (x0 < WG);
        const bool xv1 = (x0 + 1 >= 0) && (x0 + 1 < WG);
        const bool yv0 = (y0 >= 0)     && (y0 < HG);
        const bool yv1 = (y0 + 1 >= 0) && (y0 + 1 < HG);

        if (yv0 && xv0) acc += w00 * vbase[(size_t)(y0 * WG + x0) * D];
        if (yv0 && xv1) acc += w01 * vbase[(size_t)(y0 * WG + x0 + 1) * D];
        if (yv1 && xv0) acc += w10 * vbase[(size_t)((y0 + 1) * WG + x0) * D];
        if (yv1 && xv1) acc += w11 * vbase[(size_t)((y0 + 1) * WG + x0 + 1) * D];
    }
    __nv_bfloat16 h, l;
    f2bf2(acc, h, l);
    ohi[(size_t)p * D + hh * 32 + lane] = h;
    olo[(size_t)p * D + hh * 32 + lane] = l;
}

// LayerNorm + ReLU, writes bf16 hi/lo; one warp per row
template<int WID>
__global__ void ln_relu_kernel(const float* __restrict__ x,
                               const float* __restrict__ g,
                               const float* __restrict__ b,
                               __nv_bfloat16* __restrict__ ohi,
                               __nv_bfloat16* __restrict__ olo)
{
    const int row  = (blockIdx.x * blockDim.x + threadIdx.x) >> 5;
    const int lane = threadIdx.x & 31;
    if (row >= NQ) return;
    const float* xr = x + (size_t)row * WID;
    constexpr int PER = WID / 32;
    float v[PER];
    float s = 0.f, s2 = 0.f;
#pragma unroll
    for (int i = 0; i < PER; i++) {
        v[i] = xr[lane + 32 * i];
        s  += v[i];
        s2 += v[i] * v[i];
    }
#pragma unroll
    for (int o = 16; o > 0; o >>= 1) {
        s  += __shfl_xor_sync(0xffffffffu, s,  o);
        s2 += __shfl_xor_sync(0xffffffffu, s2, o);
    }
    const float mean = s / WID;
    const float var  = s2 / WID - mean * mean;
    const float inv  = rsqrtf(var + 1e-5f);
#pragma unroll
    for (int i = 0; i < PER; i++) {
        const int c = lane + 32 * i;
        const float o = fmaxf((v[i] - mean) * inv * g[c] + b[c], 0.f);
        __nv_bfloat16 h, l;
        f2bf2(o, h, l);
        ohi[(size_t)row * WID + c] = h;
        olo[(size_t)row * WID + c] = l;
    }
}

void* devptr(const void* symbol)
{
    void* p = nullptr;
    cudaGetSymbolAddress(&p, symbol);
    return p;
}

} // anonymous namespace

// ===========================================================================
// Launch sequence
// ===========================================================================
extern "C" void kernel_launch(void* const* d_in, const int* in_sizes, int n_in,
                              void* d_out, int out_size)
{
    const float* query      = (const float*)d_in[0];
    const float* value      = (const float*)d_in[1];
    const float* conv_q_w   = (const float*)d_in[2];
    const float* conv_q_b   = (const float*)d_in[3];
    const float* conv_v_w   = (const float*)d_in[4];
    const float* conv_v_b   = (const float*)d_in[5];
    const float* row_embed  = (const float*)d_in[6];
    const float* col_embed  = (const float*)d_in[7];
    const float* lin_q_w    = (const float*)d_in[8];
    const float* lin_q_b    = (const float*)d_in[9];
    const float* lin_v_w    = (const float*)d_in[10];
    const float* lin_v_b    = (const float*)d_in[11];
    const float* msda_off_w = (const float*)d_in[12];
    const float* msda_off_b = (const float*)d_in[13];
    const float* msda_aw_w  = (const float*)d_in[14];
    const float* msda_aw_b  = (const float*)d_in[15];
    const float* msda_vp_w  = (const float*)d_in[16];
    const float* msda_vp_b  = (const float*)d_in[17];
    const float* msda_op_w  = (const float*)d_in[18];
    const float* msda_op_b  = (const float*)d_in[19];
    const float* out_w1     = (const float*)d_in[20];
    const float* out_b1     = (const float*)d_in[21];
    const float* ln1_g      = (const float*)d_in[22];
    const float* ln1_b      = (const float*)d_in[23];
    const float* out_w2     = (const float*)d_in[24];
    const float* out_b2     = (const float*)d_in[25];
    const float* ln2_g      = (const float*)d_in[26];
    const float* ln2_b      = (const float*)d_in[27];
    const float* out_w3     = (const float*)d_in[28];
    const float* out_b3     = (const float*)d_in[29];

    float* pos  = (float*)devptr(g_pos);
    float* q    = (float*)devptr(g_q);
    float* valb = (float*)devptr(g_val);
    float* offb = (float*)devptr(g_off);
    float* awb  = (float*)devptr(g_aw);
    float* h1f  = (float*)devptr(g_h1f);
    float* h2f  = (float*)devptr(g_h2f);

    __nv_bfloat16* cq_h = (__nv_bfloat16*)devptr(g_cq_h);
    __nv_bfloat16* cq_l = (__nv_bfloat16*)devptr(g_cq_l);
    __nv_bfloat16* cv_h = (__nv_bfloat16*)devptr(g_cv_h);
    __nv_bfloat16* cv_l = (__nv_bfloat16*)devptr(g_cv_l);
    __nv_bfloat16* t_h  = (__nv_bfloat16*)devptr(g_t_h);
    __nv_bfloat16* t_l  = (__nv_bfloat16*)devptr(g_t_l);
    __nv_bfloat16* vb_h = (__nv_bfloat16*)devptr(g_vb_h);
    __nv_bfloat16* vb_l = (__nv_bfloat16*)devptr(g_vb_l);
    __nv_bfloat16* qb_h = (__nv_bfloat16*)devptr(g_qb_h);
    __nv_bfloat16* qb_l = (__nv_bfloat16*)devptr(g_qb_l);
    __nv_bfloat16* qp_h = (__nv_bfloat16*)devptr(g_qp_h);
    __nv_bfloat16* qp_l = (__nv_bfloat16*)devptr(g_qp_l);
    __nv_bfloat16* sp_h = (__nv_bfloat16*)devptr(g_sp_h);
    __nv_bfloat16* sp_l = (__nv_bfloat16*)devptr(g_sp_l);
    __nv_bfloat16* h1_h = (__nv_bfloat16*)devptr(g_h1_h);
    __nv_bfloat16* h1_l = (__nv_bfloat16*)devptr(g_h1_l);
    __nv_bfloat16* h2_h = (__nv_bfloat16*)devptr(g_h2_h);
    __nv_bfloat16* h2_l = (__nv_bfloat16*)devptr(g_h2_l);
    __nv_bfloat16* w_h  = (__nv_bfloat16*)devptr(g_w_h);
    __nv_bfloat16* w_l  = (__nv_bfloat16*)devptr(g_w_l);

    const dim3 blk(256);

    // weights -> bf16 hi/lo [N,K]
    WPtrs wp;
    wp.p[0] = conv_q_w; wp.p[1] = conv_v_w; wp.p[2] = lin_q_w; wp.p[3] = lin_v_w;
    wp.p[4] = msda_vp_w; wp.p[5] = msda_off_w; wp.p[6] = msda_aw_w; wp.p[7] = msda_op_w;
    wp.p[8] = out_w1; wp.p[9] = out_w2; wp.p[10] = out_w3;
    convert_weights_kernel<<<(W_TOTAL + 255) / 256, blk>>>(wp, w_h, w_l);

    pos_kernel<<<(NQ * D + 255) / 256, blk>>>(row_embed, col_embed, pos);

    // conv inputs (channel-major) -> bf16 hi/lo [M, 384]
    tconvert_kernel<<<dim3(NQ / 32, CINC / 32), dim3(32, 8)>>>(query, cq_h, cq_l, NQ, CINC);
    tconvert_kernel<<<dim3(NQ / 32, CINC / 32), dim3(32, 8)>>>(value, cv_h, cv_l, NQ, CINC);

    // conv_q -> t (bf16), lin_q -> q (fp32)
    gemm_mma<64, false, true, false, false><<<dim3(4, 128), blk>>>(
        cq_h, cq_l, w_h + W_CONVQ, w_l + W_CONVQ, conv_q_b, nullptr,
        nullptr, t_h, t_l, NQ, D, CINC);
    gemm_mma<64, true, false, false, false><<<dim3(4, 128), blk>>>(
        t_h, t_l, w_h + W_LINQ, w_l + W_LINQ, lin_q_b, nullptr,
        q, nullptr, nullptr, NQ, D, D);
    // conv_v -> t (bf16), lin_v -> v (bf16)
    gemm_mma<64, false, true, false, false><<<dim3(4, 128), blk>>>(
        cv_h, cv_l, w_h + W_CONVV, w_l + W_CONVV, conv_v_b, nullptr,
        nullptr, t_h, t_l, NQ, D, CINC);
    gemm_mma<64, false, true, false, false><<<dim3(4, 128), blk>>>(
        t_h, t_l, w_h + W_LINV, w_l + W_LINV, lin_v_b, nullptr,
        nullptr, vb_h, vb_l, NQ, D, D);

    // 4 MSDeformAttn layers (3 cross + 1 self)
    for (int i = 0; i < 4; i++) {
        const __nv_bfloat16* vin_h = (i < 3) ? vb_h : qb_h;
        const __nv_bfloat16* vin_l = (i < 3) ? vb_l : qb_l;

        add_pos_convert_kernel<<<(NQ * D + 255) / 256, blk>>>(q, pos, qp_h, qp_l);

        gemm_mma<64, true, false, false, false><<<dim3(4, 128), blk>>>(
            vin_h, vin_l, w_h + W_VP + i * 65536, w_l + W_VP + i * 65536,
            msda_vp_b + (size_t)i * D, nullptr, valb, nullptr, nullptr, NQ, D, D);

        gemm_mma<64, true, false, false, false><<<dim3(1, 128), blk>>>(
            qp_h, qp_l, w_h + W_OFF + i * 16384, w_l + W_OFF + i * 16384,
            msda_off_b + (size_t)i * 64, nullptr, offb, nullptr, nullptr, NQ, 64, D);

        gemm_mma<32, true, false, false, false><<<dim3(1, 128), blk>>>(
            qp_h, qp_l, w_h + W_AW + i * 8192, w_l + W_AW + i * 8192,
            msda_aw_b + (size_t)i * 32, nullptr, awb, nullptr, nullptr, NQ, 32, D);

        softmax4_kernel<<<(NQ * NHD + 255) / 256, blk>>>(awb);

        msda_sample_kernel<<<(NQ * NHD * 32 + 255) / 256, blk>>>(valb, offb, awb, sp_h, sp_l);

        if (i >= 2) {
            gemm_mma<64, true, true, true, false><<<dim3(4, 128), blk>>>(
                sp_h, sp_l, w_h + W_OP + i * 65536, w_l + W_OP + i * 65536,
                msda_op_b + (size_t)i * D, q, q, qb_h, qb_l, NQ, D, D);
        } else {
            gemm_mma<64, true, false, true, false><<<dim3(4, 128), blk>>>(
                sp_h, sp_l, w_h + W_OP + i * 65536, w_l + W_OP + i * 65536,
                msda_op_b + (size_t)i * D, q, q, nullptr, nullptr, NQ, D, D);
        }
    }

    // output MLP: 256 -> 128 (LN+ReLU) -> 64 (LN+ReLU) -> 384 (transposed store)
    gemm_mma<64, true, false, false, false><<<dim3(2, 128), blk>>>(
        qb_h, qb_l, w_h + W_O1, w_l + W_O1, out_b1, nullptr,
        h1f, nullptr, nullptr, NQ, 128, D);
    ln_relu_kernel<128><<<(NQ * 32 + 255) / 256, blk>>>(h1f, ln1_g, ln1_b, h1_h, h1_l);
    gemm_mma<64, true, false, false, false><<<dim3(1, 128), blk>>>(
        h1_h, h1_l, w_h + W_O2, w_l + W_O2, out_b2, nullptr,
        h2f, nullptr, nullptr, NQ, 64, 128);
    ln_relu_kernel<64><<<(NQ * 32 + 255) / 256, blk>>>(h2f, ln2_g, ln2_b, h2_h, h2_l);
    gemm_mma<64, true, false, false, true><<<dim3(6, 128), blk>>>(
        h2_h, h2_l, w_h + W_O3, w_l + W_O3, out_b3, nullptr,
        (float*)d_out, nullptr, nullptr, NQ, CINC, 64);
}

// round 14
// speedup vs baseline: 2.1169x; 1.0874x over previous
#include <cuda_runtime.h>
#include <cuda_bf16.h>
#include <cstdint>
#include <math.h>

namespace {

// ===========================================================================
// Warp-MMA helpers (baseline PTX, works on plain sm_103 target)
// ===========================================================================
__device__ __forceinline__ uint32_t smem_to_u32(const void* smem_ptr) {
    uint32_t addr;
    asm("{ .reg .u64 tmp; cvta.to.shared.u64 tmp, %1; cvt.u32.u64 %0, tmp; }"
        : "=r"(addr) : "l"(smem_ptr));
    return addr;
}

#define SMEM_SWIZZLE_128B(byte_offset) \
    ((byte_offset) ^ (((byte_offset) >> 3) & 0x70))

__device__ __forceinline__ void ldsm4(uint32_t* r, uint32_t addr) {
    asm volatile("ldmatrix.sync.aligned.m8n8.x4.shared.b16 {%0,%1,%2,%3}, [%4];"
                 : "=r"(r[0]), "=r"(r[1]), "=r"(r[2]), "=r"(r[3]) : "r"(addr));
}

__device__ __forceinline__ void mma16816(float* c, const uint32_t* a, const uint32_t* b) {
    asm volatile(
        "mma.sync.aligned.m16n8k16.row.col.f32.bf16.bf16.f32 "
        "{%0,%1,%2,%3}, {%4,%5,%6,%7}, {%8,%9}, {%0,%1,%2,%3};"
        : "+f"(c[0]), "+f"(c[1]), "+f"(c[2]), "+f"(c[3])
        : "r"(a[0]), "r"(a[1]), "r"(a[2]), "r"(a[3]), "r"(b[0]), "r"(b[1]));
}

__device__ __forceinline__ void cp16(uint32_t dst_smem, const void* src) {
    asm volatile("cp.async.cg.shared.global [%0], [%1], 16;"
                 :: "r"(dst_smem), "l"(__cvta_generic_to_global(src)) : "memory");
}

// ===========================================================================
// Problem constants + scratch
// ===========================================================================
constexpr int HG  = 128;
constexpr int WG  = 128;
constexpr int NQ  = HG * WG;        // 16384
constexpr int D   = 256;
constexpr int NHD = 8;
constexpr int CINC = 384;

// converted-weight buffer offsets (elements)
constexpr int W_CONVQ = 0;                       // 256x384
constexpr int W_CONVV = 98304;                   // 256x384
constexpr int W_LINQ  = 196608;                  // 256x256
constexpr int W_LINV  = 262144;                  // 256x256
constexpr int W_VP    = 327680;                  // 4 x 256x256
constexpr int W_OFF   = 589824;                  // 4 x 64x256
constexpr int W_AW    = 655360;                  // 4 x 32x256
constexpr int W_OP    = 688128;                  // 4 x 256x256
constexpr int W_O1    = 950272;                  // 128x256
constexpr int W_O2    = 983040;                  // 64x128
constexpr int W_O3    = 991232;                  // 384x64
constexpr int W_TOTAL = 1015808;

// fp32 scratch
__device__ float g_pos [NQ * D];
__device__ float g_q   [NQ * D];
__device__ float g_val [NQ * D];
__device__ float g_off [NQ * 64];
__device__ float g_aw  [NQ * 32];
__device__ float g_h1f [NQ * 128];
__device__ float g_h2f [NQ * 64];

// bf16 hi/lo scratch
__device__ __nv_bfloat16 g_cq_h[NQ * CINC], g_cq_l[NQ * CINC];
__device__ __nv_bfloat16 g_cv_h[NQ * CINC], g_cv_l[NQ * CINC];
__device__ __nv_bfloat16 g_t_h [NQ * D],    g_t_l [NQ * D];
__device__ __nv_bfloat16 g_vb_h[NQ * D],    g_vb_l[NQ * D];
__device__ __nv_bfloat16 g_qb_h[NQ * D],    g_qb_l[NQ * D];
__device__ __nv_bfloat16 g_qp_h[NQ * D],    g_qp_l[NQ * D];
__device__ __nv_bfloat16 g_sp_h[NQ * D],    g_sp_l[NQ * D];
__device__ __nv_bfloat16 g_h1_h[NQ * 128],  g_h1_l[NQ * 128];
__device__ __nv_bfloat16 g_h2_h[NQ * 64],   g_h2_l[NQ * 64];
__device__ __nv_bfloat16 g_w_h [W_TOTAL],   g_w_l [W_TOTAL];

__device__ __forceinline__ void f2bf2(float v, __nv_bfloat16& h, __nv_bfloat16& l)
{
    h = __float2bfloat16(v);
    l = __float2bfloat16(v - __bfloat162float(h));
}

// ===========================================================================
// Tensor-core split-bf16 GEMM via mma.sync + cp.async double buffering:
//   C[M,N] = A@B^T + bias (+res), A hi/lo [M,K] row, B hi/lo [N,K] row.
//   Block tile 128 x BN, 8 warps (4m x 2n), warp tile 32 x (BN/2).
//   K-chunk 64 halves (one SW128 row of 128 bytes), 2-stage cp.async pipeline.
//   3 products: hi*hi + hi*lo + lo*hi, fp32 accumulate in registers.
// ===========================================================================
template<int BN, bool WF32, bool WBF16, bool RES, bool STORE_T>
__global__ void __launch_bounds__(256)
gemm_mma(const __nv_bfloat16* __restrict__ Ahi, const __nv_bfloat16* __restrict__ Alo,
         const __nv_bfloat16* __restrict__ Bhi, const __nv_bfloat16* __restrict__ Blo,
         const float* __restrict__ bias, const float* __restrict__ res,
         float* __restrict__ C, __nv_bfloat16* __restrict__ Chi,
         __nv_bfloat16* __restrict__ Clo, int M, int N, int K)
{
    constexpr int WNT = BN / 2;      // warp n-tile (32 or 16)
    constexpr int NF  = WNT / 8;     // n8 fragments per warp (4 or 2)
    constexpr int OFF_ALO = 16384;
    constexpr int OFF_BHI = 32768;
    constexpr int OFF_BLO = 32768 + BN * 128;
    constexpr int STAGE   = 32768 + 2 * BN * 128;

    extern __shared__ char dynsmem[];
    const uint32_t smem_u32 = smem_to_u32(dynsmem);

    const int tid  = threadIdx.x;
    const int lane = tid & 31;
    const int wid  = tid >> 5;
    const int wm   = wid & 3;        // warp m index (0..3)
    const int wn   = wid >> 2;       // warp n index (0..1)
    const int m0   = blockIdx.y * 128;
    const int n0   = blockIdx.x * BN;

    float acc[2][NF][4];
#pragma unroll
    for (int i = 0; i < 2; i++)
#pragma unroll
        for (int j = 0; j < NF; j++)
#pragma unroll
            for (int k = 0; k < 4; k++) acc[i][j][k] = 0.f;

    // ldmatrix lane-address components
    const int a_row = (lane & 7) + ((lane >> 3) & 1) * 8;   // row within m16
    const int a_koff = (lane >> 4) * 8;                     // k-half offset
    const int b_row = (lane >> 4) * 8 + (lane & 7);         // n within 16-row pair
    const int b_koff = ((lane >> 3) & 1) * 8;

    // ---- async chunk loader: A (2 halves x 128 rows) + B (2 halves x BN rows)
    auto load_chunk = [&](int stage, int k0) {
        const uint32_t base = smem_u32 + stage * STAGE;
#pragma unroll
        for (int u = tid; u < 2048; u += 256) {
            const int half = u >> 10;
            const int uu   = u & 1023;
            const int row  = uu >> 3;
            const int c16  = uu & 7;
            const __nv_bfloat16* src =
                (half ? Alo : Ahi) + (size_t)(m0 + row) * K + k0 + c16 * 8;
            cp16(base + (half ? OFF_ALO : 0) +
                 SMEM_SWIZZLE_128B(row * 128 + c16 * 16), src);
        }
#pragma unroll
        for (int u = tid; u < 2 * BN * 8; u += 256) {
            const int half = (u >= BN * 8);
            const int uu   = half ? u - BN * 8 : u;
            const int row  = uu >> 3;
            const int c16  = uu & 7;
            const __nv_bfloat16* src =
                (half ? Blo : Bhi) + (size_t)(n0 + row) * K + k0 + c16 * 8;
            cp16(base + (half ? OFF_BLO : OFF_BHI) +
                 SMEM_SWIZZLE_128B(row * 128 + c16 * 16), src);
        }
        asm volatile("cp.async.commit_group;" ::: "memory");
    };

    const int nchunks = K >> 6;
    load_chunk(0, 0);

    for (int c = 0; c < nchunks; c++) {
        if (c + 1 < nchunks) {
            load_chunk((c + 1) & 1, (c + 1) << 6);
            asm volatile("cp.async.wait_group 1;" ::: "memory");
        } else {
            asm volatile("cp.async.wait_group 0;" ::: "memory");
        }
        __syncthreads();

        const uint32_t base = smem_u32 + (c & 1) * STAGE;
        const uint32_t sA0 = base;
        const uint32_t sA1 = base + OFF_ALO;
        const uint32_t sB0 = base + OFF_BHI;
        const uint32_t sB1 = base + OFF_BLO;

        // ---- 4 k16 steps
#pragma unroll
        for (int ks = 0; ks < 4; ks++) {
            const int kw = ks * 16;
            uint32_t ah[2][4], al[2][4];
#pragma unroll
            for (int mb = 0; mb < 2; mb++) {
                const int row = wm * 32 + mb * 16 + a_row;
                const uint32_t off = SMEM_SWIZZLE_128B(row * 128 + (kw + a_koff) * 2);
                ldsm4(ah[mb], sA0 + off);
                ldsm4(al[mb], sA1 + off);
            }
            uint32_t bh[NF][2], bl[NF][2];
#pragma unroll
            for (int pr = 0; pr < NF / 2; pr++) {
                const int row = wn * WNT + pr * 16 + b_row;
                const uint32_t off = SMEM_SWIZZLE_128B(row * 128 + (kw + b_koff) * 2);
                uint32_t t[4];
                ldsm4(t, sB0 + off);
                bh[pr * 2][0] = t[0]; bh[pr * 2][1] = t[1];
                bh[pr * 2 + 1][0] = t[2]; bh[pr * 2 + 1][1] = t[3];
                ldsm4(t, sB1 + off);
                bl[pr * 2][0] = t[0]; bl[pr * 2][1] = t[1];
                bl[pr * 2 + 1][0] = t[2]; bl[pr * 2 + 1][1] = t[3];
            }
#pragma unroll
            for (int mb = 0; mb < 2; mb++)
#pragma unroll
                for (int nf = 0; nf < NF; nf++) {
                    mma16816(acc[mb][nf], ah[mb], bh[nf]);
                    mma16816(acc[mb][nf], ah[mb], bl[nf]);
                    mma16816(acc[mb][nf], al[mb], bh[nf]);
                }
        }
        __syncthreads();
    }

    // ---- epilogue ---------------------------------------------------------
#pragma unroll
    for (int mb = 0; mb < 2; mb++) {
#pragma unroll
        for (int part = 0; part < 2; part++) {
            const int m = m0 + wm * 32 + mb * 16 + part * 8 + (lane >> 2);
#pragma unroll
            for (int nf = 0; nf < NF; nf++) {
                const int col = n0 + wn * WNT + nf * 8 + (lane & 3) * 2;
                float v0 = acc[mb][nf][part * 2 + 0] + bias[col];
                float v1 = acc[mb][nf][part * 2 + 1] + bias[col + 1];
                if (RES) {
                    const float2 r2 = *(const float2*)(res + (size_t)m * N + col);
                    v0 += r2.x; v1 += r2.y;
                }
                if (STORE_T) {
                    C[(size_t)col * M + m] = v0;
                    C[(size_t)(col + 1) * M + m] = v1;
                } else if (WF32) {
                    *(float2*)(C + (size_t)m * N + col) = make_float2(v0, v1);
                }
                if (WBF16) {
                    __nv_bfloat16 h0, l0, h1, l1;
                    f2bf2(v0, h0, l0);
                    f2bf2(v1, h1, l1);
                    Chi[(size_t)m * N + col] = h0; Chi[(size_t)m * N + col + 1] = h1;
                    Clo[(size_t)m * N + col] = l0; Clo[(size_t)m * N + col + 1] = l1;
                }
            }
        }
    }
}

// ===========================================================================
// Elementwise / conversion kernels
// ===========================================================================
__global__ void pos_kernel(const float* __restrict__ row_embed,
                           const float* __restrict__ col_embed,
                           float* __restrict__ pos)
{
    const int idx = blockIdx.x * blockDim.x + threadIdx.x;
    if (idx >= NQ * D) return;
    const int p = idx >> 8;
    const int d = idx & 255;
    const int h = p >> 7;
    const int w = p & 127;
    pos[idx] = (d < 128) ? col_embed[w * 128 + d] : row_embed[h * 128 + (d - 128)];
}

// channel-major fp32 [K,M] -> hi/lo bf16 [M,K] (32x32 smem transpose tiles)
__global__ void tconvert_kernel(const float* __restrict__ src,
                                __nv_bfloat16* __restrict__ hi,
                                __nv_bfloat16* __restrict__ lo, int M, int K)
{
    __shared__ float t[32][33];
    const int tx = threadIdx.x, ty = threadIdx.y;
    const int m0 = blockIdx.x * 32, k0 = blockIdx.y * 32;
#pragma unroll
    for (int j = 0; j < 4; j++)
        t[ty + j * 8][tx] = src[(size_t)(k0 + ty + j * 8) * M + m0 + tx];
    __syncthreads();
#pragma unroll
    for (int j = 0; j < 4; j++) {
        const int m = m0 + ty + j * 8;
        const int k = k0 + tx;
        __nv_bfloat16 h, l;
        f2bf2(t[tx][ty + j * 8], h, l);
        hi[(size_t)m * K + k] = h;
        lo[(size_t)m * K + k] = l;
    }
}

// one-shot conversion of all weight matrices into [N,K] hi/lo bf16
struct WSeg { int srcSel; int srcOff; int N; int K; int kn; int dstOff; };
__device__ const WSeg d_wsegs[23] = {
    {0, 0,      256, 384, 0, W_CONVQ},
    {1, 0,      256, 384, 0, W_CONVV},
    {2, 0,      256, 256, 1, W_LINQ},
    {3, 0,      256, 256, 1, W_LINV},
    {4, 0,      256, 256, 1, W_VP + 0 * 65536},
    {4, 65536,  256, 256, 1, W_VP + 1 * 65536},
    {4, 131072, 256, 256, 1, W_VP + 2 * 65536},
    {4, 196608, 256, 256, 1, W_VP + 3 * 65536},
    {5, 0,      64, 256, 1, W_OFF + 0 * 16384},
    {5, 16384,  64, 256, 1, W_OFF + 1 * 16384},
    {5, 32768,  64, 256, 1, W_OFF + 2 * 16384},
    {5, 49152,  64, 256, 1, W_OFF + 3 * 16384},
    {6, 0,      32, 256, 1, W_AW + 0 * 8192},
    {6, 8192,   32, 256, 1, W_AW + 1 * 8192},
    {6, 16384,  32, 256, 1, W_AW + 2 * 8192},
    {6, 24576,  32, 256, 1, W_AW + 3 * 8192},
    {7, 0,      256, 256, 1, W_OP + 0 * 65536},
    {7, 65536,  256, 256, 1, W_OP + 1 * 65536},
    {7, 131072, 256, 256, 1, W_OP + 2 * 65536},
    {7, 196608, 256, 256, 1, W_OP + 3 * 65536},
    {8, 0,      128, 256, 1, W_O1},
    {9, 0,      64, 128, 1, W_O2},
    {10, 0,     384, 64, 1, W_O3},
};
struct WPtrs { const float* p[11]; };

__global__ void convert_weights_kernel(WPtrs ptrs,
                                       __nv_bfloat16* __restrict__ hi,
                                       __nv_bfloat16* __restrict__ lo)
{
    const int id = blockIdx.x * blockDim.x + threadIdx.x;
    if (id >= W_TOTAL) return;
    int s = 0;
#pragma unroll
    for (int i = 1; i < 23; i++)
        if (id >= d_wsegs[i].dstOff) s = i;
    const WSeg seg = d_wsegs[s];
    const int local = id - seg.dstOff;
    const int n = local / seg.K;
    const int k = local - n * seg.K;
    const float* src = ptrs.p[seg.srcSel] + seg.srcOff;
    const float v = seg.kn ? src[(size_t)k * seg.N + n] : src[(size_t)n * seg.K + k];
    __nv_bfloat16 h, l;
    f2bf2(v, h, l);
    hi[id] = h;
    lo[id] = l;
}

__global__ void add_pos_convert_kernel(const float* __restrict__ q,
                                       const float* __restrict__ pos,
                                       __nv_bfloat16* __restrict__ hi,
                                       __nv_bfloat16* __restrict__ lo)
{
    const int i = blockIdx.x * blockDim.x + threadIdx.x;
    if (i >= NQ * D) return;
    __nv_bfloat16 h, l;
    f2bf2(q[i] + pos[i], h, l);
    hi[i] = h;
    lo[i] = l;
}

__global__ void softmax4_kernel(float* __restrict__ aw)
{
    const int t = blockIdx.x * blockDim.x + threadIdx.x;
    if (t >= NQ * NHD) return;
    float4 v = ((const float4*)aw)[t];
    const float mx = fmaxf(fmaxf(v.x, v.y), fmaxf(v.z, v.w));
    const float ex = __expf(v.x - mx), ey = __expf(v.y - mx);
    const float ez = __expf(v.z - mx), ew = __expf(v.w - mx);
    const float r = 1.f / (ex + ey + ez + ew);
    ((float4*)aw)[t] = make_float4(ex * r, ey * r, ez * r, ew * r);
}

// one warp per (query, head); lane = channel; writes samp as bf16 hi/lo
__global__ void msda_sample_kernel(const float* __restrict__ val,
                                   const float* __restrict__ off,
                                   const float* __restrict__ aw,
                                   __nv_bfloat16* __restrict__ ohi,
                                   __nv_bfloat16* __restrict__ olo)
{
    const int warp = (blockIdx.x * blockDim.x + threadIdx.x) >> 5;
    const int lane = threadIdx.x & 31;
    if (warp >= NQ * NHD) return;
    const int p = warp >> 3;
    const int hh = warp & 7;
    const int py = p >> 7;
    const int px = p & 127;

    const float* offp  = off + (size_t)p * 64 + hh * 8;
    const float* awp   = aw  + (size_t)p * 32 + hh * 4;
    const float* vbase = val + hh * 32 + lane;

    float acc = 0.f;
#pragma unroll
    for (int k = 0; k < 4; k++) {
        const float a  = awp[k];
        const float x  = (float)px + offp[2 * k + 0];
        const float y  = (float)py + offp[2 * k + 1];
        const float xf = floorf(x), yf = floorf(y);
        const float lx = x - xf,   ly = y - yf;
        const int   x0 = (int)xf,  y0 = (int)yf;

        const float w00 = (1.f - lx) * (1.f - ly) * a;
        const float w01 = lx * (1.f - ly) * a;
        const float w10 = (1.f - lx) * ly * a;
        const float w11 = lx * ly * a;

        const bool xv0 = (x0 >= 0)     && (x0 < WG);
        const bool xv1 = (x0 + 1 >= 0) && (x0 + 1 < WG);
        const bool yv0 = (y0 >= 0)     && (y0 < HG);
        const bool yv1 = (y0 + 1 >= 0) && (y0 + 1 < HG);

        if (yv0 && xv0) acc += w00 * vbase[(size_t)(y0 * WG + x0) * D];
        if (yv0 && xv1) acc += w01 * vbase[(size_t)(y0 * WG + x0 + 1) * D];
        if (yv1 && xv0) acc += w10 * vbase[(size_t)((y0 + 1) * WG + x0) * D];
        if (yv1 && xv1) acc += w11 * vbase[(size_t)((y0 + 1) * WG + x0 + 1) * D];
    }
    __nv_bfloat16 h, l;
    f2bf2(acc, h, l);
    ohi[(size_t)p * D + hh * 32 + lane] = h;
    olo[(size_t)p * D + hh * 32 + lane] = l;
}

// LayerNorm + ReLU, writes bf16 hi/lo; one warp per row
template<int WID>
__global__ void ln_relu_kernel(const float* __restrict__ x,
                               const float* __restrict__ g,
                               const float* __restrict__ b,
                               __nv_bfloat16* __restrict__ ohi,
                               __nv_bfloat16* __restrict__ olo)
{
    const int row  = (blockIdx.x * blockDim.x + threadIdx.x) >> 5;
    const int lane = threadIdx.x & 31;
    if (row >= NQ) return;
    const float* xr = x + (size_t)row * WID;
    constexpr int PER = WID / 32;
    float v[PER];
    float s = 0.f, s2 = 0.f;
#pragma unroll
    for (int i = 0; i < PER; i++) {
        v[i] = xr[lane + 32 * i];
        s  += v[i];
        s2 += v[i] * v[i];
    }
#pragma unroll
    for (int o = 16; o > 0; o >>= 1) {
        s  += __shfl_xor_sync(0xffffffffu, s,  o);
        s2 += __shfl_xor_sync(0xffffffffu, s2, o);
    }
    const float mean = s / WID;
    const float var  = s2 / WID - mean * mean;
    const float inv  = rsqrtf(var + 1e-5f);
#pragma unroll
    for (int i = 0; i < PER; i++) {
        const int c = lane + 32 * i;
        const float o = fmaxf((v[i] - mean) * inv * g[c] + b[c], 0.f);
        __nv_bfloat16 h, l;
        f2bf2(o, h, l);
        ohi[(size_t)row * WID + c] = h;
        olo[(size_t)row * WID + c] = l;
    }
}

void* devptr(const void* symbol)
{
    void* p = nullptr;
    cudaGetSymbolAddress(&p, symbol);
    return p;
}

constexpr int SMEM64 = 2 * (32768 + 2 * 64 * 128);   // 98304
constexpr int SMEM32 = 2 * (32768 + 2 * 32 * 128);   // 81920

} // anonymous namespace

// ===========================================================================
// Launch sequence
// ===========================================================================
extern "C" void kernel_launch(void* const* d_in, const int* in_sizes, int n_in,
                              void* d_out, int out_size)
{
    const float* query      = (const float*)d_in[0];
    const float* value      = (const float*)d_in[1];
    const float* conv_q_w   = (const float*)d_in[2];
    const float* conv_q_b   = (const float*)d_in[3];
    const float* conv_v_w   = (const float*)d_in[4];
    const float* conv_v_b   = (const float*)d_in[5];
    const float* row_embed  = (const float*)d_in[6];
    const float* col_embed  = (const float*)d_in[7];
    const float* lin_q_w    = (const float*)d_in[8];
    const float* lin_q_b    = (const float*)d_in[9];
    const float* lin_v_w    = (const float*)d_in[10];
    const float* lin_v_b    = (const float*)d_in[11];
    const float* msda_off_w = (const float*)d_in[12];
    const float* msda_off_b = (const float*)d_in[13];
    const float* msda_aw_w  = (const float*)d_in[14];
    const float* msda_aw_b  = (const float*)d_in[15];
    const float* msda_vp_w  = (const float*)d_in[16];
    const float* msda_vp_b  = (const float*)d_in[17];
    const float* msda_op_w  = (const float*)d_in[18];
    const float* msda_op_b  = (const float*)d_in[19];
    const float* out_w1     = (const float*)d_in[20];
    const float* out_b1     = (const float*)d_in[21];
    const float* ln1_g      = (const float*)d_in[22];
    const float* ln1_b      = (const float*)d_in[23];
    const float* out_w2     = (const float*)d_in[24];
    const float* out_b2     = (const float*)d_in[25];
    const float* ln2_g      = (const float*)d_in[26];
    const float* ln2_b      = (const float*)d_in[27];
    const float* out_w3     = (const float*)d_in[28];
    const float* out_b3     = (const float*)d_in[29];

    float* pos  = (float*)devptr(g_pos);
    float* q    = (float*)devptr(g_q);
    float* valb = (float*)devptr(g_val);
    float* offb = (float*)devptr(g_off);
    float* awb  = (float*)devptr(g_aw);
    float* h1f  = (float*)devptr(g_h1f);
    float* h2f  = (float*)devptr(g_h2f);

    __nv_bfloat16* cq_h = (__nv_bfloat16*)devptr(g_cq_h);
    __nv_bfloat16* cq_l = (__nv_bfloat16*)devptr(g_cq_l);
    __nv_bfloat16* cv_h = (__nv_bfloat16*)devptr(g_cv_h);
    __nv_bfloat16* cv_l = (__nv_bfloat16*)devptr(g_cv_l);
    __nv_bfloat16* t_h  = (__nv_bfloat16*)devptr(g_t_h);
    __nv_bfloat16* t_l  = (__nv_bfloat16*)devptr(g_t_l);
    __nv_bfloat16* vb_h = (__nv_bfloat16*)devptr(g_vb_h);
    __nv_bfloat16* vb_l = (__nv_bfloat16*)devptr(g_vb_l);
    __nv_bfloat16* qb_h = (__nv_bfloat16*)devptr(g_qb_h);
    __nv_bfloat16* qb_l = (__nv_bfloat16*)devptr(g_qb_l);
    __nv_bfloat16* qp_h = (__nv_bfloat16*)devptr(g_qp_h);
    __nv_bfloat16* qp_l = (__nv_bfloat16*)devptr(g_qp_l);
    __nv_bfloat16* sp_h = (__nv_bfloat16*)devptr(g_sp_h);
    __nv_bfloat16* sp_l = (__nv_bfloat16*)devptr(g_sp_l);
    __nv_bfloat16* h1_h = (__nv_bfloat16*)devptr(g_h1_h);
    __nv_bfloat16* h1_l = (__nv_bfloat16*)devptr(g_h1_l);
    __nv_bfloat16* h2_h = (__nv_bfloat16*)devptr(g_h2_h);
    __nv_bfloat16* h2_l = (__nv_bfloat16*)devptr(g_h2_l);
    __nv_bfloat16* w_h  = (__nv_bfloat16*)devptr(g_w_h);
    __nv_bfloat16* w_l  = (__nv_bfloat16*)devptr(g_w_l);

    const dim3 blk(256);

    // raise dynamic smem limits (host-side attribute set; capture-safe)
    cudaFuncSetAttribute(gemm_mma<64, false, true,  false, false>, cudaFuncAttributeMaxDynamicSharedMemorySize, SMEM64);
    cudaFuncSetAttribute(gemm_mma<64, true,  false, false, false>, cudaFuncAttributeMaxDynamicSharedMemorySize, SMEM64);
    cudaFuncSetAttribute(gemm_mma<64, true,  true,  true,  false>, cudaFuncAttributeMaxDynamicSharedMemorySize, SMEM64);
    cudaFuncSetAttribute(gemm_mma<64, true,  false, true,  false>, cudaFuncAttributeMaxDynamicSharedMemorySize, SMEM64);
    cudaFuncSetAttribute(gemm_mma<64, true,  false, false, true >, cudaFuncAttributeMaxDynamicSharedMemorySize, SMEM64);
    cudaFuncSetAttribute(gemm_mma<32, true,  false, false, false>, cudaFuncAttributeMaxDynamicSharedMemorySize, SMEM32);

    // weights -> bf16 hi/lo [N,K]
    WPtrs wp;
    wp.p[0] = conv_q_w; wp.p[1] = conv_v_w; wp.p[2] = lin_q_w; wp.p[3] = lin_v_w;
    wp.p[4] = msda_vp_w; wp.p[5] = msda_off_w; wp.p[6] = msda_aw_w; wp.p[7] = msda_op_w;
    wp.p[8] = out_w1; wp.p[9] = out_w2; wp.p[10] = out_w3;
    convert_weights_kernel<<<(W_TOTAL + 255) / 256, blk>>>(wp, w_h, w_l);

    pos_kernel<<<(NQ * D + 255) / 256, blk>>>(row_embed, col_embed, pos);

    // conv inputs (channel-major) -> bf16 hi/lo [M, 384]
    tconvert_kernel<<<dim3(NQ / 32, CINC / 32), dim3(32, 8)>>>(query, cq_h, cq_l, NQ, CINC);
    tconvert_kernel<<<dim3(NQ / 32, CINC / 32), dim3(32, 8)>>>(value, cv_h, cv_l, NQ, CINC);

    // conv_q -> t (bf16), lin_q -> q (fp32)
    gemm_mma<64, false, true, false, false><<<dim3(4, 128), blk, SMEM64>>>(
        cq_h, cq_l, w_h + W_CONVQ, w_l + W_CONVQ, conv_q_b, nullptr,
        nullptr, t_h, t_l, NQ, D, CINC);
    gemm_mma<64, true, false, false, false><<<dim3(4, 128), blk, SMEM64>>>(
        t_h, t_l, w_h + W_LINQ, w_l + W_LINQ, lin_q_b, nullptr,
        q, nullptr, nullptr, NQ, D, D);
    // conv_v -> t (bf16), lin_v -> v (bf16)
    gemm_mma<64, false, true, false, false><<<dim3(4, 128), blk, SMEM64>>>(
        cv_h, cv_l, w_h + W_CONVV, w_l + W_CONVV, conv_v_b, nullptr,
        nullptr, t_h, t_l, NQ, D, CINC);
    gemm_mma<64, false, true, false, false><<<dim3(4, 128), blk, SMEM64>>>(
        t_h, t_l, w_h + W_LINV, w_l + W_LINV, lin_v_b, nullptr,
        nullptr, vb_h, vb_l, NQ, D, D);

    // 4 MSDeformAttn layers (3 cross + 1 self)
    for (int i = 0; i < 4; i++) {
        const __nv_bfloat16* vin_h = (i < 3) ? vb_h : qb_h;
        const __nv_bfloat16* vin_l = (i < 3) ? vb_l : qb_l;

        add_pos_convert_kernel<<<(NQ * D + 255) / 256, blk>>>(q, pos, qp_h, qp_l);

        gemm_mma<64, true, false, false, false><<<dim3(4, 128), blk, SMEM64>>>(
            vin_h, vin_l, w_h + W_VP + i * 65536, w_l + W_VP + i * 65536,
            msda_vp_b + (size_t)i * D, nullptr, valb, nullptr, nullptr, NQ, D, D);

        gemm_mma<64, true, false, false, false><<<dim3(1, 128), blk, SMEM64>>>(
            qp_h, qp_l, w_h + W_OFF + i * 16384, w_l + W_OFF + i * 16384,
            msda_off_b + (size_t)i * 64, nullptr, offb, nullptr, nullptr, NQ, 64, D);

        gemm_mma<32, true, false, false, false><<<dim3(1, 128), blk, SMEM32>>>(
            qp_h, qp_l, w_h + W_AW + i * 8192, w_l + W_AW + i * 8192,
            msda_aw_b + (size_t)i * 32, nullptr, awb, nullptr, nullptr, NQ, 32, D);

        softmax4_kernel<<<(NQ * NHD + 255) / 256, blk>>>(awb);

        msda_sample_kernel<<<(NQ * NHD * 32 + 255) / 256, blk>>>(valb, offb, awb, sp_h, sp_l);

        if (i >= 2) {
            gemm_mma<64, true, true, true, false><<<dim3(4, 128), blk, SMEM64>>>(
                sp_h, sp_l, w_h + W_OP + i * 65536, w_l + W_OP + i * 65536,
                msda_op_b + (size_t)i * D, q, q, qb_h, qb_l, NQ, D, D);
        } else {
            gemm_mma<64, true, false, true, false><<<dim3(4, 128), blk, SMEM64>>>(
                sp_h, sp_l, w_h + W_OP + i * 65536, w_l + W_OP + i * 65536,
                msda_op_b + (size_t)i * D, q, q, nullptr, nullptr, NQ, D, D);
        }
    }

    // output MLP: 256 -> 128 (LN+ReLU) -> 64 (LN+ReLU) -> 384 (transposed store)
    gemm_mma<64, true, false, false, false><<<dim3(2, 128), blk, SMEM64>>>(
        qb_h, qb_l, w_h + W_O1, w_l + W_O1, out_b1, nullptr,
        h1f, nullptr, nullptr, NQ, 128, D);
    ln_relu_kernel<128><<<(NQ * 32 + 255) / 256, blk>>>(h1f, ln1_g, ln1_b, h1_h, h1_l);
    gemm_mma<64, true, false, false, false><<<dim3(1, 128), blk, SMEM64>>>(
        h1_h, h1_l, w_h + W_O2, w_l + W_O2, out_b2, nullptr,
        h2f, nullptr, nullptr, NQ, 64, 128);
    ln_relu_kernel<64><<<(NQ * 32 + 255) / 256, blk>>>(h2f, ln2_g, ln2_b, h2_h, h2_l);
    gemm_mma<64, true, false, false, true><<<dim3(6, 128), blk, SMEM64>>>(
        h2_h, h2_l, w_h + W_O3, w_l + W_O3, out_b3, nullptr,
        (float*)d_out, nullptr, nullptr, NQ, CINC, 64);
}